// round 1
// baseline (speedup 1.0000x reference)
#include <cuda_runtime.h>
#include <math_constants.h>

// Problem constants (fixed by this benchmark's shapes)
#define NQ    50000   // candidates per instance
#define BQ    512     // queries per instance
#define EDIM  16
#define KSEL  20      // neighbors kept (top_k K+1 minus self)
#define QG    16      // queries per CTA (register-reuse factor for emb loads)
#define NSPLIT 8      // N-dimension splits
#define CHUNK (NQ / NSPLIT)   // 6250
#define SCAN_THREADS 256
#define HID   64

// ---- static device scratch (no dynamic allocation allowed) ----
__device__ float g_ee[2][NQ];                    // ||emb_j||^2 per instance
__device__ float g_key[2][BQ][NSPLIT][KSEL];     // partial top-20 keys (ee - 2*dot)
__device__ int   g_cid[2][BQ][NSPLIT][KSEL];     // partial top-20 candidate indices

// ============================================================
// Kernel 1: candidate squared norms
// ============================================================
__global__ void ee_kernel(const float* __restrict__ emb0,
                          const float* __restrict__ emb1) {
    int i = blockIdx.x * blockDim.x + threadIdx.x;
    if (i >= 2 * NQ) return;
    int inst = i / NQ, j = i % NQ;
    const float* e = (inst ? emb1 : emb0) + (size_t)j * EDIM;
    float s = 0.f;
#pragma unroll
    for (int d = 0; d < EDIM; d++) s = fmaf(e[d], e[d], s);
    g_ee[inst][j] = s;
}

// ============================================================
// Kernel 2: register-blocked distance scan + threshold top-20
// grid = 64 query-groups * NSPLIT;  block = 256
// ============================================================
__global__ void __launch_bounds__(SCAN_THREADS)
scan_kernel(const float* __restrict__ emb0, const float* __restrict__ emb1,
            const int* __restrict__ idx0, const int* __restrict__ idx1) {
    __shared__ float4 sh_q4[QG][4];        // query vectors (16B aligned)
    __shared__ float  sh_key[QG][KSEL];    // current best keys (protected by lock)
    __shared__ int    sh_kid[QG][KSEL];
    __shared__ float  sh_thr[QG];          // current max of list (monotone down)
    __shared__ int    sh_lock[QG];
    __shared__ int    sh_self[QG];

    int grp   = blockIdx.x / NSPLIT;       // 0..63
    int split = blockIdx.x % NSPLIT;
    int inst  = grp >> 5;                  // 32 groups per instance
    int qbase = (grp & 31) * QG;
    const float* emb  = inst ? emb1 : emb0;
    const int*   idxp = inst ? idx1 : idx0;
    const float* ee   = g_ee[inst];
    int base = split * CHUNK;
    int t = threadIdx.x;

    // load QG query vectors + self indices
    {
        int q = t >> 4, d = t & 15;        // 256 threads = QG*16 exactly
        int si = idxp[qbase + q];
        if (d == 0) { sh_self[q] = si; sh_lock[q] = 0; }
        ((float*)&sh_q4[q][0])[d] = emb[(size_t)si * EDIM + d];
    }
    __syncthreads();

    // seed lists with first KSEL candidates of this chunk (lock-free)
    for (int t2 = t; t2 < QG * KSEL; t2 += SCAN_THREADS) {
        int q = t2 / KSEL, s = t2 % KSEL;
        int j = base + s;
        const float* qv = (const float*)&sh_q4[q][0];
        float dot = 0.f;
#pragma unroll
        for (int d = 0; d < EDIM; d++)
            dot = fmaf(qv[d], emb[(size_t)j * EDIM + d], dot);
        float key = fmaf(-2.f, dot, ee[j]);
        if (j == sh_self[q]) key = CUDART_INF_F;   // exclude self
        sh_key[q][s] = key;
        sh_kid[q][s] = j;
    }
    __syncthreads();
    if (t < QG) {
        float mx = -CUDART_INF_F;
#pragma unroll
        for (int s = 0; s < KSEL; s++) mx = fmaxf(mx, sh_key[t][s]);
        sh_thr[t] = mx;
    }
    __syncthreads();

    const float4* emb4 = (const float4*)emb;
    volatile float* vthr = sh_thr;

    // main scan: each thread owns one candidate, tests it against QG queries
    for (int j = base + KSEL + t; j < base + CHUNK; j += SCAN_THREADS) {
        float4 e0 = emb4[(size_t)j * 4 + 0];
        float4 e1 = emb4[(size_t)j * 4 + 1];
        float4 e2 = emb4[(size_t)j * 4 + 2];
        float4 e3 = emb4[(size_t)j * 4 + 3];
        float eej = ee[j];
#pragma unroll
        for (int q = 0; q < QG; q++) {
            float4 a0 = sh_q4[q][0], a1 = sh_q4[q][1];
            float4 a2 = sh_q4[q][2], a3 = sh_q4[q][3];
            float p0 = a0.x * e0.x, p1 = a0.y * e0.y;
            float p2 = a0.z * e0.z, p3 = a0.w * e0.w;
            p0 = fmaf(a1.x, e1.x, p0); p1 = fmaf(a1.y, e1.y, p1);
            p2 = fmaf(a1.z, e1.z, p2); p3 = fmaf(a1.w, e1.w, p3);
            p0 = fmaf(a2.x, e2.x, p0); p1 = fmaf(a2.y, e2.y, p1);
            p2 = fmaf(a2.z, e2.z, p2); p3 = fmaf(a2.w, e2.w, p3);
            p0 = fmaf(a3.x, e3.x, p0); p1 = fmaf(a3.y, e3.y, p1);
            p2 = fmaf(a3.z, e3.z, p2); p3 = fmaf(a3.w, e3.w, p3);
            float dot = (p0 + p1) + (p2 + p3);
            float key = fmaf(-2.f, dot, eej);
            if (key < vthr[q]) {
                // rare path: locked insertion into the top-20 list
                if (j != sh_self[q]) {
                    bool done = false;
                    while (!done) {
                        if (atomicExch(&sh_lock[q], 1) == 0) {
                            __threadfence_block();
                            float mx = sh_key[q][0]; int ms = 0;
#pragma unroll
                            for (int s = 1; s < KSEL; s++) {
                                float v = sh_key[q][s];
                                if (v > mx) { mx = v; ms = s; }
                            }
                            if (key < mx) {
                                sh_key[q][ms] = key;
                                sh_kid[q][ms] = j;
                                float nm = -CUDART_INF_F;
#pragma unroll
                                for (int s = 0; s < KSEL; s++)
                                    nm = fmaxf(nm, sh_key[q][s]);
                                sh_thr[q] = nm;
                            }
                            __threadfence_block();
                            atomicExch(&sh_lock[q], 0);
                            done = true;
                        }
                    }
                }
            }
        }
    }
    __syncthreads();

    // write partial results
    for (int t2 = t; t2 < QG * KSEL; t2 += SCAN_THREADS) {
        int q = t2 / KSEL, s = t2 % KSEL;
        int b = qbase + q;
        g_key[inst][b][split][s] = sh_key[q][s];
        g_cid[inst][b][split][s] = sh_kid[q][s];
    }
}

// ============================================================
// Kernel 3: merge partials, compute features, run MLP
// grid = BQ blocks, 64 threads (warp0 -> inst0, warp1 -> inst1)
// ============================================================
#define NCAND (NSPLIT * KSEL)   // 160

__global__ void __launch_bounds__(HID)
merge_kernel(const float* __restrict__ rctx0, const float* __restrict__ rctx1,
             const int* __restrict__ idx0, const int* __restrict__ idx1,
             const float* __restrict__ mean_in, const float* __restrict__ std_in,
             const float* __restrict__ W1, const float* __restrict__ b1v,
             const float* __restrict__ Wm, const float* __restrict__ bm,
             const float* __restrict__ Ws, const float* __restrict__ bs,
             float* __restrict__ out) {
    __shared__ float sh_feat[8];
    __shared__ float sh_selk[2][KSEL];
    __shared__ int   sh_seli[2][KSEL];
    __shared__ float sh_red[4];

    int b = blockIdx.x;
    int t = threadIdx.x;
    int w = t >> 5;
    int lane = t & 31;

    {
        int inst = w;   // warp 0 -> instance 0, warp 1 -> instance 1
        const float* keys = &g_key[inst][b][0][0];
        const int*   cids = &g_cid[inst][b][0][0];
        float k[5]; int id[5];
#pragma unroll
        for (int s = 0; s < 5; s++) {
            int p = lane + 32 * s;   // 160 = 32*5
            k[s] = keys[p]; id[s] = cids[p];
        }
        // 20 sequential warp argmins over 160 candidates
        for (int iter = 0; iter < KSEL; iter++) {
            float bv = k[0]; int bslot = 0;
#pragma unroll
            for (int s = 1; s < 5; s++)
                if (k[s] < bv) { bv = k[s]; bslot = s; }
            float v = bv; int owner = lane;
#pragma unroll
            for (int off = 16; off > 0; off >>= 1) {
                float ov = __shfl_down_sync(0xffffffffu, v, off);
                int   ol = __shfl_down_sync(0xffffffffu, owner, off);
                if (ov < v) { v = ov; owner = ol; }
            }
            owner = __shfl_sync(0xffffffffu, owner, 0);
            if (lane == owner) {
                sh_selk[inst][iter] = k[bslot];
                sh_seli[inst][iter] = id[bslot];
                k[bslot] = CUDART_INF_F;
            }
            __syncwarp();
        }
        __syncwarp();

        // features over the 20 selected neighbors
        const float* rctx = inst ? rctx1 : rctx0;
        const int*   idxp = inst ? idx1 : idx0;
        float aa = g_ee[inst][idxp[b]];
        float wsum = 0.f, swsum = 0.f, ssum = 0.f, s2sum = 0.f;
        if (lane < KSEL) {
            float d2 = sh_selk[inst][lane] + aa;   // ee - 2dot + aa
            d2 = fmaxf(d2, 0.f);
            float sim = sqrtf(d2) + 0.001f;
            float ww = expf(-sim);
            float sel = rctx[(size_t)b * NQ + sh_seli[inst][lane]];
            wsum = ww; swsum = sel * ww; ssum = sel; s2sum = sel * sel;
        }
#pragma unroll
        for (int off = 16; off > 0; off >>= 1) {
            wsum  += __shfl_down_sync(0xffffffffu, wsum,  off);
            swsum += __shfl_down_sync(0xffffffffu, swsum, off);
            ssum  += __shfl_down_sync(0xffffffffu, ssum,  off);
            s2sum += __shfl_down_sync(0xffffffffu, s2sum, off);
        }
        if (lane == 0) {
            float f1 = wsum;
            float f2 = swsum / wsum;
            float var = (s2sum - ssum * ssum / (float)KSEL) / (float)(KSEL - 1);
            float f3 = sqrtf(fmaxf(var, 0.f));
            sh_feat[0 + inst] = f1;   // stack order: a1,b1,a2,b2,a3,b3,mean,std
            sh_feat[2 + inst] = f2;
            sh_feat[4 + inst] = f3;
            if (inst == 0) { sh_feat[6] = mean_in[b]; sh_feat[7] = std_in[b]; }
        }
    }
    __syncthreads();

    // MLP: 8 -> 64 (relu) -> 2
    float h = b1v[t];
#pragma unroll
    for (int i = 0; i < 8; i++) h = fmaf(sh_feat[i], W1[i * HID + t], h);
    h = fmaxf(h, 0.f);
    float pm = h * Wm[t];
    float ps = h * Ws[t];
#pragma unroll
    for (int off = 16; off > 0; off >>= 1) {
        pm += __shfl_down_sync(0xffffffffu, pm, off);
        ps += __shfl_down_sync(0xffffffffu, ps, off);
    }
    if (lane == 0) { sh_red[w * 2] = pm; sh_red[w * 2 + 1] = ps; }
    __syncthreads();
    if (t == 0) {
        out[b]      = sh_red[0] + sh_red[2] + bm[0];
        out[BQ + b] = sh_red[1] + sh_red[3] + bs[0];
    }
}

// ============================================================
extern "C" void kernel_launch(void* const* d_in, const int* in_sizes, int n_in,
                              void* d_out, int out_size) {
    const float* emb0    = (const float*)d_in[0];
    const float* emb1    = (const float*)d_in[1];
    const float* rctx0   = (const float*)d_in[2];
    const float* rctx1   = (const float*)d_in[3];
    const int*   idx0    = (const int*)d_in[4];
    const int*   idx1    = (const int*)d_in[5];
    const float* mean_in = (const float*)d_in[6];
    const float* std_in  = (const float*)d_in[7];
    const float* W1      = (const float*)d_in[8];
    const float* b1v     = (const float*)d_in[9];
    const float* Wm      = (const float*)d_in[10];
    const float* bm      = (const float*)d_in[11];
    const float* Ws      = (const float*)d_in[12];
    const float* bs      = (const float*)d_in[13];
    float* out = (float*)d_out;

    ee_kernel<<<(2 * NQ + 255) / 256, 256>>>(emb0, emb1);
    scan_kernel<<<(2 * BQ / QG) * NSPLIT, SCAN_THREADS>>>(emb0, emb1, idx0, idx1);
    merge_kernel<<<BQ, HID>>>(rctx0, rctx1, idx0, idx1, mean_in, std_in,
                              W1, b1v, Wm, bm, Ws, bs, out);
}

// round 2
// speedup vs baseline: 7.8416x; 7.8416x over previous
#include <cuda_runtime.h>
#include <math_constants.h>

// Problem constants (fixed by this benchmark's shapes)
#define NQ    50000
#define BQ    512
#define EDIM  16
#define KSEL  20
#define QG    16               // queries per CTA
#define NSPLIT 12              // N-dimension splits -> grid 64*12 = 768
#define CHUNK ((NQ + NSPLIT - 1) / NSPLIT)   // 4167
#define SCAN_THREADS 256
#define SEG   256              // candidates per segment (== blockDim)
#define HID   64
#define NCAND (NSPLIT * KSEL)  // 240
#define LSTR  21               // padded list stride (bank-conflict-free)

typedef unsigned long long u64;

// static device scratch
__device__ float g_key[2][BQ][NSPLIT][KSEL];
__device__ int   g_cid[2][BQ][NSPLIT][KSEL];

// ---- packed f32x2 helpers (Blackwell FFMA2) ----
__device__ __forceinline__ u64 mul2(u64 a, u64 b) {
    u64 d; asm("mul.rn.f32x2 %0,%1,%2;" : "=l"(d) : "l"(a), "l"(b)); return d;
}
__device__ __forceinline__ u64 fma2(u64 a, u64 b, u64 c) {
    u64 d; asm("fma.rn.f32x2 %0,%1,%2,%3;" : "=l"(d) : "l"(a), "l"(b), "l"(c)); return d;
}
__device__ __forceinline__ u64 add2(u64 a, u64 b) {
    u64 d; asm("add.rn.f32x2 %0,%1,%2;" : "=l"(d) : "l"(a), "l"(b)); return d;
}
__device__ __forceinline__ float hsum2(u64 v) {
    float lo, hi; asm("mov.b64 {%0,%1},%2;" : "=f"(lo), "=f"(hi) : "l"(v));
    return lo + hi;
}

// ============================================================
// Scan kernel: register-blocked distance scan, lock-free
// deferred top-20 selection via per-query shared queues.
// grid = 64 query-groups * NSPLIT, block = 256
// ============================================================
__global__ void __launch_bounds__(SCAN_THREADS)
scan_kernel(const float* __restrict__ emb0, const float* __restrict__ emb1,
            const int* __restrict__ idx0, const int* __restrict__ idx1) {
    __shared__ ulonglong2 sh_q[QG][4];        // query vectors (16 floats each)
    __shared__ float sh_lk[QG * LSTR];        // top-20 keys per query
    __shared__ int   sh_li[QG * LSTR];        // top-20 ids per query
    __shared__ float sh_thr[QG];              // current list max per query
    __shared__ int   sh_self[QG];
    __shared__ int   sh_cnt[QG];              // queue counters
    __shared__ float sh_bk[QG][SEG + 1];      // queue keys   (padded rows)
    __shared__ int   sh_bj[QG][SEG + 1];      // queue ids

    int grp   = blockIdx.x / NSPLIT;          // 0..63
    int split = blockIdx.x % NSPLIT;
    int inst  = grp >> 5;
    int qbase = (grp & 31) * QG;
    const float* emb  = inst ? emb1 : emb0;
    const int*   idxp = inst ? idx1 : idx0;
    const ulonglong2* e2 = (const ulonglong2*)emb;
    int base = split * CHUNK;
    int end  = min(base + CHUNK, NQ);
    int t = threadIdx.x;

    // init: queries, lists, thresholds, counters
    {
        int q = t >> 4, d = t & 15;           // 256 = QG*16 exactly
        int si = idxp[qbase + q];
        if (d == 0) { sh_self[q] = si; sh_cnt[q] = 0; sh_thr[q] = CUDART_INF_F; }
        ((float*)&sh_q[q][0])[d] = emb[(size_t)si * EDIM + d];
        if (d < 8) {                           // 16*8 = 128 >= QG*KSEL/ ... cover 20 slots
            // fill list slots via strided loop below instead
        }
    }
    for (int p = t; p < QG * KSEL; p += SCAN_THREADS) {
        int q = p / KSEL, s = p % KSEL;
        sh_lk[q * LSTR + s] = CUDART_INF_F;
        sh_li[q * LSTR + s] = 0;
    }
    __syncthreads();

    float thr[QG];
#pragma unroll
    for (int q = 0; q < QG; q++) thr[q] = CUDART_INF_F;

    // per-owner selection state (only threads with t%16==0 use these)
    float cmax = CUDART_INF_F;
    int   cslot = 0;

    unsigned lanelt = (1u << (t & 31)) - 1u;

    for (int s0 = base; s0 < end; s0 += SEG) {
        int j = s0 + t;
        bool valid = j < end;
        int jc = valid ? j : base;             // safe load index

        // load candidate embedding (16 floats = 8 f32x2)
        u64 c0, c1, c2, c3, c4, c5, c6, c7;
        {
            ulonglong2 u0 = e2[(size_t)jc * 4 + 0];
            ulonglong2 u1 = e2[(size_t)jc * 4 + 1];
            ulonglong2 u2 = e2[(size_t)jc * 4 + 2];
            ulonglong2 u3 = e2[(size_t)jc * 4 + 3];
            c0 = u0.x; c1 = u0.y; c2 = u1.x; c3 = u1.y;
            c4 = u2.x; c5 = u2.y; c6 = u3.x; c7 = u3.y;
        }
        // candidate squared norm (inline; INF disables invalid lanes)
        u64 eA = mul2(c0, c0); eA = fma2(c1, c1, eA);
        eA = fma2(c2, c2, eA); eA = fma2(c3, c3, eA);
        u64 eB = mul2(c4, c4); eB = fma2(c5, c5, eB);
        eB = fma2(c6, c6, eB); eB = fma2(c7, c7, eB);
        float ee = hsum2(add2(eA, eB));
        if (!valid) ee = CUDART_INF_F;

#pragma unroll
        for (int q = 0; q < QG; q++) {
            ulonglong2 v0 = sh_q[q][0], v1 = sh_q[q][1];
            ulonglong2 v2 = sh_q[q][2], v3 = sh_q[q][3];
            u64 sA = mul2(c0, v0.x); sA = fma2(c1, v0.y, sA);
            sA = fma2(c2, v1.x, sA); sA = fma2(c3, v1.y, sA);
            u64 sB = mul2(c4, v2.x); sB = fma2(c5, v2.y, sB);
            sB = fma2(c6, v3.x, sB); sB = fma2(c7, v3.y, sB);
            float dot = hsum2(add2(sA, sB));
            float key = fmaf(-2.f, dot, ee);   // = ||e||^2 - 2 a.e  (INF if invalid)
            bool pass = key < thr[q];
            unsigned m = __ballot_sync(0xffffffffu, pass);
            if (m) {                            // uniform branch
                int leader = __ffs(m) - 1;
                int p0 = 0;
                if ((t & 31) == leader) p0 = atomicAdd(&sh_cnt[q], __popc(m));
                p0 = __shfl_sync(0xffffffffu, p0, leader);
                if (pass) {
                    int r = p0 + __popc(m & lanelt);
                    sh_bk[q][r] = key;
                    sh_bj[q][r] = j;
                }
            }
        }
        __syncthreads();

        // queue drain: 16 owner threads, 2 per warp
        if ((t & 15) == 0) {
            int q = t >> 4;
            int n = sh_cnt[q];
            sh_cnt[q] = 0;
            int selfq = sh_self[q];
            float* lk = &sh_lk[q * LSTR];
            int*   li = &sh_li[q * LSTR];
            for (int i = 0; i < n; i++) {
                float k = sh_bk[q][i];
                if (k < cmax) {
                    int jj = sh_bj[q][i];
                    if (jj != selfq) {
                        lk[cslot] = k; li[cslot] = jj;
                        float mx = -CUDART_INF_F; int ms = 0;
#pragma unroll
                        for (int s = 0; s < KSEL; s++) {
                            float v = lk[s];
                            if (v > mx) { mx = v; ms = s; }
                        }
                        cmax = mx; cslot = ms;
                    }
                }
            }
            sh_thr[q] = cmax;
        }
        __syncthreads();
#pragma unroll
        for (int q = 0; q < QG; q++) thr[q] = sh_thr[q];
    }

    // write partial top-20 lists
    for (int p = t; p < QG * KSEL; p += SCAN_THREADS) {
        int q = p / KSEL, s = p % KSEL;
        int b = qbase + q;
        g_key[inst][b][split][s] = sh_lk[q * LSTR + s];
        g_cid[inst][b][split][s] = sh_li[q * LSTR + s];
    }
}

// ============================================================
// Merge kernel: merge partials, features, MLP
// grid = BQ blocks, 64 threads (warp0 -> inst0, warp1 -> inst1)
// ============================================================
#define NCH 8   // ceil(NCAND/32)

__global__ void __launch_bounds__(HID)
merge_kernel(const float* __restrict__ emb0, const float* __restrict__ emb1,
             const float* __restrict__ rctx0, const float* __restrict__ rctx1,
             const int* __restrict__ idx0, const int* __restrict__ idx1,
             const float* __restrict__ mean_in, const float* __restrict__ std_in,
             const float* __restrict__ W1, const float* __restrict__ b1v,
             const float* __restrict__ Wm, const float* __restrict__ bm,
             const float* __restrict__ Ws, const float* __restrict__ bs,
             float* __restrict__ out) {
    __shared__ float sh_feat[8];
    __shared__ float sh_selk[2][KSEL];
    __shared__ int   sh_seli[2][KSEL];
    __shared__ float sh_red[4];

    int b = blockIdx.x;
    int t = threadIdx.x;
    int w = t >> 5;
    int lane = t & 31;

    {
        int inst = w;
        const float* embp = inst ? emb1 : emb0;
        const int*   idxp = inst ? idx1 : idx0;
        int self = idxp[b];

        // query squared norm via warp reduction
        float av = (lane < EDIM) ? embp[(size_t)self * EDIM + lane] : 0.f;
        float aa = av * av;
#pragma unroll
        for (int off = 16; off > 0; off >>= 1)
            aa += __shfl_down_sync(0xffffffffu, aa, off);
        aa = __shfl_sync(0xffffffffu, aa, 0);

        const float* keys = &g_key[inst][b][0][0];
        const int*   cids = &g_cid[inst][b][0][0];
        float k[NCH]; int id[NCH];
#pragma unroll
        for (int s = 0; s < NCH; s++) {
            int p = lane + 32 * s;
            if (p < NCAND) { k[s] = keys[p]; id[s] = cids[p]; }
            else           { k[s] = CUDART_INF_F; id[s] = 0; }
        }
        // 20 sequential warp argmins over 240 candidates
        for (int iter = 0; iter < KSEL; iter++) {
            float bv = k[0]; int bslot = 0;
#pragma unroll
            for (int s = 1; s < NCH; s++)
                if (k[s] < bv) { bv = k[s]; bslot = s; }
            float v = bv; int owner = lane;
#pragma unroll
            for (int off = 16; off > 0; off >>= 1) {
                float ov = __shfl_down_sync(0xffffffffu, v, off);
                int   ol = __shfl_down_sync(0xffffffffu, owner, off);
                if (ov < v) { v = ov; owner = ol; }
            }
            owner = __shfl_sync(0xffffffffu, owner, 0);
            if (lane == owner) {
                sh_selk[inst][iter] = k[bslot];
                sh_seli[inst][iter] = id[bslot];
                k[bslot] = CUDART_INF_F;
            }
            __syncwarp();
        }
        __syncwarp();

        // features over the 20 selected neighbors
        const float* rctx = inst ? rctx1 : rctx0;
        float wsum = 0.f, swsum = 0.f, ssum = 0.f, s2sum = 0.f;
        if (lane < KSEL) {
            float d2 = sh_selk[inst][lane] + aa;
            d2 = fmaxf(d2, 0.f);
            float sim = sqrtf(d2) + 0.001f;
            float ww = expf(-sim);
            float sel = rctx[(size_t)b * NQ + sh_seli[inst][lane]];
            wsum = ww; swsum = sel * ww; ssum = sel; s2sum = sel * sel;
        }
#pragma unroll
        for (int off = 16; off > 0; off >>= 1) {
            wsum  += __shfl_down_sync(0xffffffffu, wsum,  off);
            swsum += __shfl_down_sync(0xffffffffu, swsum, off);
            ssum  += __shfl_down_sync(0xffffffffu, ssum,  off);
            s2sum += __shfl_down_sync(0xffffffffu, s2sum, off);
        }
        if (lane == 0) {
            float f1 = wsum;
            float f2 = swsum / wsum;
            float var = (s2sum - ssum * ssum / (float)KSEL) / (float)(KSEL - 1);
            float f3 = sqrtf(fmaxf(var, 0.f));
            sh_feat[0 + inst] = f1;
            sh_feat[2 + inst] = f2;
            sh_feat[4 + inst] = f3;
            if (inst == 0) { sh_feat[6] = mean_in[b]; sh_feat[7] = std_in[b]; }
        }
    }
    __syncthreads();

    // MLP: 8 -> 64 (relu) -> 2
    float h = b1v[t];
#pragma unroll
    for (int i = 0; i < 8; i++) h = fmaf(sh_feat[i], W1[i * HID + t], h);
    h = fmaxf(h, 0.f);
    float pm = h * Wm[t];
    float ps = h * Ws[t];
#pragma unroll
    for (int off = 16; off > 0; off >>= 1) {
        pm += __shfl_down_sync(0xffffffffu, pm, off);
        ps += __shfl_down_sync(0xffffffffu, ps, off);
    }
    if (lane == 0) { sh_red[w * 2] = pm; sh_red[w * 2 + 1] = ps; }
    __syncthreads();
    if (t == 0) {
        out[b]      = sh_red[0] + sh_red[2] + bm[0];
        out[BQ + b] = sh_red[1] + sh_red[3] + bs[0];
    }
}

// ============================================================
extern "C" void kernel_launch(void* const* d_in, const int* in_sizes, int n_in,
                              void* d_out, int out_size) {
    const float* emb0    = (const float*)d_in[0];
    const float* emb1    = (const float*)d_in[1];
    const float* rctx0   = (const float*)d_in[2];
    const float* rctx1   = (const float*)d_in[3];
    const int*   idx0    = (const int*)d_in[4];
    const int*   idx1    = (const int*)d_in[5];
    const float* mean_in = (const float*)d_in[6];
    const float* std_in  = (const float*)d_in[7];
    const float* W1      = (const float*)d_in[8];
    const float* b1v     = (const float*)d_in[9];
    const float* Wm      = (const float*)d_in[10];
    const float* bm      = (const float*)d_in[11];
    const float* Ws      = (const float*)d_in[12];
    const float* bs      = (const float*)d_in[13];
    float* out = (float*)d_out;

    scan_kernel<<<64 * NSPLIT, SCAN_THREADS>>>(emb0, emb1, idx0, idx1);
    merge_kernel<<<BQ, HID>>>(emb0, emb1, rctx0, rctx1, idx0, idx1,
                              mean_in, std_in, W1, b1v, Wm, bm, Ws, bs, out);
}

// round 5
// speedup vs baseline: 8.0118x; 1.0217x over previous
#include <cuda_runtime.h>
#include <math_constants.h>

#define NQ    50000
#define BQ    512
#define EDIM  16
#define KSEL  20
#define QG    16               // queries per CTA
#define NSPLIT 12              // grid = 64*12 = 768
#define CHUNK ((NQ + NSPLIT - 1) / NSPLIT)   // 4167
#define SCAN_THREADS 256
#define SEG   256
#define HID   64
#define NCAND (NSPLIT * KSEL)  // 240
#define LSTR  21
#define MROWS 4                // merge rows per CTA

typedef unsigned long long u64;

__device__ float g_key[2][BQ][NSPLIT][KSEL];
__device__ int   g_cid[2][BQ][NSPLIT][KSEL];

// ---- packed f32x2 helpers (Blackwell FFMA2) ----
__device__ __forceinline__ u64 mul2(u64 a, u64 b) {
    u64 d; asm("mul.rn.f32x2 %0,%1,%2;" : "=l"(d) : "l"(a), "l"(b)); return d;
}
__device__ __forceinline__ u64 fma2(u64 a, u64 b, u64 c) {
    u64 d; asm("fma.rn.f32x2 %0,%1,%2,%3;" : "=l"(d) : "l"(a), "l"(b), "l"(c)); return d;
}
__device__ __forceinline__ u64 add2(u64 a, u64 b) {
    u64 d; asm("add.rn.f32x2 %0,%1,%2;" : "=l"(d) : "l"(a), "l"(b)); return d;
}
__device__ __forceinline__ float hsum2(u64 v) {
    float lo, hi; asm("mov.b64 {%0,%1},%2;" : "=f"(lo), "=f"(hi) : "l"(v));
    return lo + hi;
}
__device__ __forceinline__ u64 pack2(float lo, float hi) {
    u64 d; asm("mov.b64 %0,{%1,%2};" : "=l"(d) : "f"(lo), "f"(hi)); return d;
}

// ============================================================
// Scan kernel: vote-free masked scan + deferred queue selection
// ============================================================
__global__ void __launch_bounds__(SCAN_THREADS, 2)
scan_kernel(const float* __restrict__ emb0, const float* __restrict__ emb1,
            const int* __restrict__ idx0, const int* __restrict__ idx1) {
    __shared__ ulonglong2 sh_qs[QG][4];   // queries pre-scaled by -2, packed
    __shared__ float sh_lk[QG * LSTR];
    __shared__ int   sh_li[QG * LSTR];
    __shared__ float sh_thr[QG];
    __shared__ int   sh_self[QG];
    __shared__ int   sh_cnt[QG];
    __shared__ float sh_bk[QG][SEG];
    __shared__ int   sh_bj[QG][SEG];

    int grp   = blockIdx.x / NSPLIT;
    int split = blockIdx.x % NSPLIT;
    int inst  = grp >> 5;
    int qbase = (grp & 31) * QG;
    const float* emb  = inst ? emb1 : emb0;
    const int*   idxp = inst ? idx1 : idx0;
    const ulonglong2* e2 = (const ulonglong2*)emb;
    int base = split * CHUNK;
    int end  = min(base + CHUNK, NQ);
    int t = threadIdx.x;

    {
        int q = t >> 4, d = t & 15;        // 256 = QG*16
        int si = idxp[qbase + q];
        if (d == 0) { sh_self[q] = si; sh_cnt[q] = 0; sh_thr[q] = CUDART_INF_F; }
        ((float*)&sh_qs[q][0])[d] = -2.0f * emb[(size_t)si * EDIM + d];
    }
    for (int p = t; p < QG * KSEL; p += SCAN_THREADS) {
        int q = p / KSEL, s = p % KSEL;
        sh_lk[q * LSTR + s] = CUDART_INF_F;
        sh_li[q * LSTR + s] = 0;
    }
    __syncthreads();

    float thr[QG];
#pragma unroll
    for (int q = 0; q < QG; q++) thr[q] = CUDART_INF_F;

    // owner-thread selection state
    float cmax = CUDART_INF_F;
    int   cslot = 0;

    for (int s0 = base; s0 < end; s0 += SEG) {
        int j = s0 + t;
        bool valid = j < end;
        int jc = valid ? j : base;
        bool first = (s0 == base);

        ulonglong2 u0 = e2[(size_t)jc * 4 + 0];
        ulonglong2 u1 = e2[(size_t)jc * 4 + 1];
        ulonglong2 u2 = e2[(size_t)jc * 4 + 2];
        ulonglong2 u3 = e2[(size_t)jc * 4 + 3];
        u64 c0 = u0.x, c1 = u0.y, c2 = u1.x, c3 = u1.y;
        u64 c4 = u2.x, c5 = u2.y, c6 = u3.x, c7 = u3.y;

        // candidate squared norm
        u64 eA = mul2(c0, c0); eA = fma2(c1, c1, eA);
        eA = fma2(c2, c2, eA); eA = fma2(c3, c3, eA);
        u64 eB = mul2(c4, c4); eB = fma2(c5, c5, eB);
        eB = fma2(c6, c6, eB); eB = fma2(c7, c7, eB);
        float ee = hsum2(add2(eA, eB));
        if (!valid) ee = CUDART_INF_F;
        u64 eeinit = pack2(ee, 0.0f);

        unsigned pm = 0;
        float kk[QG];
#pragma unroll
        for (int q = 0; q < QG; q++) {
            const ulonglong2* qv = &sh_qs[q][0];
            ulonglong2 q01 = qv[0], q23 = qv[1], q45 = qv[2], q67 = qv[3];
            u64 a = fma2(c0, q01.x, eeinit);
            a = fma2(c1, q01.y, a);
            a = fma2(c2, q23.x, a);
            a = fma2(c3, q23.y, a);
            u64 bacc = mul2(c4, q45.x);
            bacc = fma2(c5, q45.y, bacc);
            bacc = fma2(c6, q67.x, bacc);
            bacc = fma2(c7, q67.y, bacc);
            float key = hsum2(add2(a, bacc));   // = ee - 2*dot
            kk[q] = key;
            pm |= (key < thr[q]) ? (1u << q) : 0u;
        }

        if (first) {
            // flood segment: every thread appends all queries at slot t
#pragma unroll
            for (int q = 0; q < QG; q++) {
                sh_bk[q][t] = kk[q];
                sh_bj[q][t] = j;
            }
        } else if (pm) {
            do {
                int q = __ffs(pm) - 1;
                pm &= pm - 1;
                int r = atomicAdd(&sh_cnt[q], 1);
                sh_bk[q][r] = kk[q];
                sh_bj[q][r] = j;
            } while (pm);
        }
        __syncthreads();

        // drain: 16 owner threads (2 per warp)
        if ((t & 15) == 0) {
            int q = t >> 4;
            int n = first ? SEG : sh_cnt[q];
            sh_cnt[q] = 0;
            int selfq = sh_self[q];
            float* lk = &sh_lk[q * LSTR];
            int*   li = &sh_li[q * LSTR];
            for (int i = 0; i < n; i++) {
                float k = sh_bk[q][i];
                if (k < cmax) {
                    int jj = sh_bj[q][i];
                    if (jj != selfq) {
                        lk[cslot] = k; li[cslot] = jj;
                        float mx = lk[0]; int ms = 0;
#pragma unroll
                        for (int s = 1; s < KSEL; s++) {
                            float v = lk[s];
                            if (v > mx) { mx = v; ms = s; }
                        }
                        cmax = mx; cslot = ms;
                    }
                }
            }
            sh_thr[q] = cmax;
        }
        __syncthreads();
#pragma unroll
        for (int q = 0; q < QG; q++) thr[q] = sh_thr[q];
    }

    for (int p = t; p < QG * KSEL; p += SCAN_THREADS) {
        int q = p / KSEL, s = p % KSEL;
        int b = qbase + q;
        g_key[inst][b][split][s] = sh_lk[q * LSTR + s];
        g_cid[inst][b][split][s] = sh_li[q * LSTR + s];
    }
}

// ============================================================
// Merge kernel: 4 rows per CTA (256 threads), features + MLP
// ============================================================
#define NCH 8   // ceil(NCAND/32)

__global__ void __launch_bounds__(256)
merge_kernel(const float* __restrict__ emb0, const float* __restrict__ emb1,
             const float* __restrict__ rctx0, const float* __restrict__ rctx1,
             const int* __restrict__ idx0, const int* __restrict__ idx1,
             const float* __restrict__ mean_in, const float* __restrict__ std_in,
             const float* __restrict__ W1, const float* __restrict__ b1v,
             const float* __restrict__ Wm, const float* __restrict__ bm,
             const float* __restrict__ Ws, const float* __restrict__ bs,
             float* __restrict__ out) {
    __shared__ float sh_feat[MROWS][8];
    __shared__ float sh_selk[MROWS][2][KSEL];
    __shared__ int   sh_seli[MROWS][2][KSEL];
    __shared__ float sh_red[MROWS][4];

    int t = threadIdx.x;
    int sb = t >> 6;                  // sub-block 0..3
    int b = blockIdx.x * MROWS + sb;
    int tl = t & 63;
    int w = tl >> 5;                  // instance
    int lane = t & 31;

    {
        int inst = w;
        const float* embp = inst ? emb1 : emb0;
        const int*   idxp = inst ? idx1 : idx0;
        int self = idxp[b];

        float av = (lane < EDIM) ? embp[(size_t)self * EDIM + lane] : 0.f;
        float aa = av * av;
#pragma unroll
        for (int off = 16; off > 0; off >>= 1)
            aa += __shfl_down_sync(0xffffffffu, aa, off);
        aa = __shfl_sync(0xffffffffu, aa, 0);

        const float* keys = &g_key[inst][b][0][0];
        const int*   cids = &g_cid[inst][b][0][0];
        float k[NCH]; int id[NCH];
#pragma unroll
        for (int s = 0; s < NCH; s++) {
            int p = lane + 32 * s;
            if (p < NCAND) { k[s] = keys[p]; id[s] = cids[p]; }
            else           { k[s] = CUDART_INF_F; id[s] = 0; }
        }
        for (int iter = 0; iter < KSEL; iter++) {
            float bv = k[0]; int bslot = 0;
#pragma unroll
            for (int s = 1; s < NCH; s++)
                if (k[s] < bv) { bv = k[s]; bslot = s; }
            float v = bv; int owner = lane;
#pragma unroll
            for (int off = 16; off > 0; off >>= 1) {
                float ov = __shfl_down_sync(0xffffffffu, v, off);
                int   ol = __shfl_down_sync(0xffffffffu, owner, off);
                if (ov < v) { v = ov; owner = ol; }
            }
            owner = __shfl_sync(0xffffffffu, owner, 0);
            if (lane == owner) {
                sh_selk[sb][inst][iter] = k[bslot];
                sh_seli[sb][inst][iter] = id[bslot];
                k[bslot] = CUDART_INF_F;
            }
            __syncwarp();
        }
        __syncwarp();

        const float* rctx = inst ? rctx1 : rctx0;
        float wsum = 0.f, swsum = 0.f, ssum = 0.f, s2sum = 0.f;
        if (lane < KSEL) {
            float d2 = sh_selk[sb][inst][lane] + aa;
            d2 = fmaxf(d2, 0.f);
            float sim = sqrtf(d2) + 0.001f;
            float ww = expf(-sim);
            float sel = rctx[(size_t)b * NQ + sh_seli[sb][inst][lane]];
            wsum = ww; swsum = sel * ww; ssum = sel; s2sum = sel * sel;
        }
#pragma unroll
        for (int off = 16; off > 0; off >>= 1) {
            wsum  += __shfl_down_sync(0xffffffffu, wsum,  off);
            swsum += __shfl_down_sync(0xffffffffu, swsum, off);
            ssum  += __shfl_down_sync(0xffffffffu, ssum,  off);
            s2sum += __shfl_down_sync(0xffffffffu, s2sum, off);
        }
        if (lane == 0) {
            float f1 = wsum;
            float f2 = swsum / wsum;
            float var = (s2sum - ssum * ssum / (float)KSEL) / (float)(KSEL - 1);
            float f3 = sqrtf(fmaxf(var, 0.f));
            sh_feat[sb][0 + inst] = f1;
            sh_feat[sb][2 + inst] = f2;
            sh_feat[sb][4 + inst] = f3;
            if (inst == 0) { sh_feat[sb][6] = mean_in[b]; sh_feat[sb][7] = std_in[b]; }
        }
    }
    __syncthreads();

    // MLP: 8 -> 64 (relu) -> 2 ; tl = hidden index
    float h = b1v[tl];
#pragma unroll
    for (int i = 0; i < 8; i++) h = fmaf(sh_feat[sb][i], W1[i * HID + tl], h);
    h = fmaxf(h, 0.f);
    float pm = h * Wm[tl];
    float ps = h * Ws[tl];
#pragma unroll
    for (int off = 16; off > 0; off >>= 1) {
        pm += __shfl_down_sync(0xffffffffu, pm, off);
        ps += __shfl_down_sync(0xffffffffu, ps, off);
    }
    if (lane == 0) { sh_red[sb][w * 2] = pm; sh_red[sb][w * 2 + 1] = ps; }
    __syncthreads();
    if (tl == 0) {
        out[b]      = sh_red[sb][0] + sh_red[sb][2] + bm[0];
        out[BQ + b] = sh_red[sb][1] + sh_red[sb][3] + bs[0];
    }
}

// ============================================================
extern "C" void kernel_launch(void* const* d_in, const int* in_sizes, int n_in,
                              void* d_out, int out_size) {
    const float* emb0    = (const float*)d_in[0];
    const float* emb1    = (const float*)d_in[1];
    const float* rctx0   = (const float*)d_in[2];
    const float* rctx1   = (const float*)d_in[3];
    const int*   idx0    = (const int*)d_in[4];
    const int*   idx1    = (const int*)d_in[5];
    const float* mean_in = (const float*)d_in[6];
    const float* std_in  = (const float*)d_in[7];
    const float* W1      = (const float*)d_in[8];
    const float* b1v     = (const float*)d_in[9];
    const float* Wm      = (const float*)d_in[10];
    const float* bm      = (const float*)d_in[11];
    const float* Ws      = (const float*)d_in[12];
    const float* bs      = (const float*)d_in[13];
    float* out = (float*)d_out;

    scan_kernel<<<64 * NSPLIT, SCAN_THREADS>>>(emb0, emb1, idx0, idx1);
    merge_kernel<<<BQ / MROWS, 256>>>(emb0, emb1, rctx0, rctx1, idx0, idx1,
                                      mean_in, std_in, W1, b1v, Wm, bm, Ws, bs, out);
}

// round 6
// speedup vs baseline: 9.3976x; 1.1730x over previous
#include <cuda_runtime.h>
#include <math_constants.h>

#define NQ    50000
#define BQ    512
#define EDIM  16
#define KSEL  20
#define QG    16                 // queries per CTA
#define QR    4                  // queries per thread (in registers)
#define NGRP  (QG / QR)          // query-slot groups = 4
#define NSPLIT 9                 // grid = 64*9 = 576 (2 waves @ occ 2)
#define CHUNK ((NQ + NSPLIT - 1) / NSPLIT)   // 5556
#define SCAN_THREADS 256
#define CLANES 64                // candidate lanes per round
#define SEGQ  256                // candidates per drain segment (4 rounds)
#define HID   64
#define NCAND (NSPLIT * KSEL)    // 180
#define NCH   6                  // ceil(NCAND/32)
#define LSTR  21
#define MROWS 4

typedef unsigned long long u64;

__device__ float g_key[2][BQ][NSPLIT][KSEL];
__device__ int   g_cid[2][BQ][NSPLIT][KSEL];

// ---- packed f32x2 helpers ----
__device__ __forceinline__ u64 mul2(u64 a, u64 b) {
    u64 d; asm("mul.rn.f32x2 %0,%1,%2;" : "=l"(d) : "l"(a), "l"(b)); return d;
}
__device__ __forceinline__ u64 fma2(u64 a, u64 b, u64 c) {
    u64 d; asm("fma.rn.f32x2 %0,%1,%2,%3;" : "=l"(d) : "l"(a), "l"(b), "l"(c)); return d;
}
__device__ __forceinline__ u64 add2(u64 a, u64 b) {
    u64 d; asm("add.rn.f32x2 %0,%1,%2;" : "=l"(d) : "l"(a), "l"(b)); return d;
}
__device__ __forceinline__ float hsum2(u64 v) {
    float lo, hi; asm("mov.b64 {%0,%1},%2;" : "=f"(lo), "=f"(hi) : "l"(v));
    return lo + hi;
}
__device__ __forceinline__ u64 pack2(float lo, float hi) {
    u64 d; asm("mov.b64 %0,{%1,%2};" : "=l"(d) : "f"(lo), "f"(hi)); return d;
}

// ============================================================
// Scan kernel: queries in REGISTERS, zero LDS in the hot loop.
// 256 threads = 64 candidate lanes x 4 query-slot groups.
// grid = 64 query-groups * NSPLIT
// ============================================================
__global__ void __launch_bounds__(SCAN_THREADS, 2)
scan_kernel(const float* __restrict__ emb0, const float* __restrict__ emb1,
            const int* __restrict__ idx0, const int* __restrict__ idx1) {
    __shared__ float sh_lk[QG * LSTR];        // top-20 keys
    __shared__ int   sh_li[QG * LSTR];        // top-20 ids
    __shared__ float sh_thr[QG];
    __shared__ int   sh_self[QG];
    __shared__ int   sh_cnt[QG];
    __shared__ float sh_bk[QG][SEGQ + 1];     // +1 pad: drain bank-conflict-free
    __shared__ int   sh_bj[QG][SEGQ + 1];

    int grp   = blockIdx.x / NSPLIT;          // 0..63
    int split = blockIdx.x % NSPLIT;
    int inst  = grp >> 5;
    int qbase = (grp & 31) * QG;
    const float* emb  = inst ? emb1 : emb0;
    const int*   idxp = inst ? idx1 : idx0;
    const ulonglong2* e2 = (const ulonglong2*)emb;
    int base = split * CHUNK;
    int end  = min(base + CHUNK, NQ);
    int t  = threadIdx.x;
    int cl = t & (CLANES - 1);                // candidate lane 0..63
    int g  = t >> 6;                          // query-slot group 0..3
    int q0 = g * QR;                          // first local query of this thread

    if (t < QG) {
        sh_self[t] = idxp[qbase + t];
        sh_cnt[t]  = 0;
        sh_thr[t]  = CUDART_INF_F;
    }
    for (int p = t; p < QG * KSEL; p += SCAN_THREADS) {
        int q = p / KSEL, s = p % KSEL;
        sh_lk[q * LSTR + s] = CUDART_INF_F;
        sh_li[q * LSTR + s] = 0;
    }
    __syncthreads();

    // load this thread's QR queries into registers, pre-scaled by -2
    u64 qr[QR][8];
#pragma unroll
    for (int i = 0; i < QR; i++) {
        int qi = sh_self[q0 + i];
        const float* qp = emb + (size_t)qi * EDIM;
#pragma unroll
        for (int d = 0; d < 8; d++)
            qr[i][d] = pack2(-2.0f * qp[2 * d], -2.0f * qp[2 * d + 1]);
    }

    float thr[QR];
#pragma unroll
    for (int i = 0; i < QR; i++) thr[i] = CUDART_INF_F;

    // owner-thread selection state (threads t%16==0)
    float cmax = CUDART_INF_F;
    int   cslot = 0;

    for (int s0 = base; s0 < end; s0 += SEGQ) {
        bool first = (s0 == base);
#pragma unroll
        for (int r = 0; r < SEGQ / CLANES; r++) {
            int j = s0 + r * CLANES + cl;
            bool valid = j < end;
            int jc = valid ? j : base;

            ulonglong2 u0 = e2[(size_t)jc * 4 + 0];
            ulonglong2 u1 = e2[(size_t)jc * 4 + 1];
            ulonglong2 u2 = e2[(size_t)jc * 4 + 2];
            ulonglong2 u3 = e2[(size_t)jc * 4 + 3];
            u64 c0 = u0.x, c1 = u0.y, c2 = u1.x, c3 = u1.y;
            u64 c4 = u2.x, c5 = u2.y, c6 = u3.x, c7 = u3.y;

            // candidate squared norm
            u64 eA = mul2(c0, c0); eA = fma2(c1, c1, eA);
            eA = fma2(c2, c2, eA); eA = fma2(c3, c3, eA);
            u64 eB = mul2(c4, c4); eB = fma2(c5, c5, eB);
            eB = fma2(c6, c6, eB); eB = fma2(c7, c7, eB);
            float ee = hsum2(add2(eA, eB));
            if (!valid) ee = CUDART_INF_F;
            u64 eeinit = pack2(ee, 0.0f);

            unsigned pm = 0;
            float kk[QR];
#pragma unroll
            for (int i = 0; i < QR; i++) {
                u64 a = fma2(c0, qr[i][0], eeinit);
                a = fma2(c1, qr[i][1], a);
                a = fma2(c2, qr[i][2], a);
                a = fma2(c3, qr[i][3], a);
                u64 bb = mul2(c4, qr[i][4]);
                bb = fma2(c5, qr[i][5], bb);
                bb = fma2(c6, qr[i][6], bb);
                bb = fma2(c7, qr[i][7], bb);
                float key = hsum2(add2(a, bb));   // = ||e||^2 - 2 a.e
                kk[i] = key;
                pm |= (key < thr[i]) ? (1u << i) : 0u;
            }

            if (first) {
                int slot = r * CLANES + cl;
#pragma unroll
                for (int i = 0; i < QR; i++) {
                    sh_bk[q0 + i][slot] = kk[i];
                    sh_bj[q0 + i][slot] = j;
                }
            } else if (pm) {
                do {
                    int i = __ffs(pm) - 1;
                    pm &= pm - 1;
                    int rr = atomicAdd(&sh_cnt[q0 + i], 1);
                    sh_bk[q0 + i][rr] = kk[i];
                    sh_bj[q0 + i][rr] = j;
                } while (pm);
            }
        }
        __syncthreads();

        // drain: 16 owner threads (2 per warp)
        if ((t & 15) == 0) {
            int q = t >> 4;
            int n = first ? SEGQ : sh_cnt[q];
            sh_cnt[q] = 0;
            int selfq = sh_self[q];
            float* lk = &sh_lk[q * LSTR];
            int*   li = &sh_li[q * LSTR];
            for (int i2 = 0; i2 < n; i2++) {
                float k = sh_bk[q][i2];
                if (k < cmax) {
                    int jj = sh_bj[q][i2];
                    if (jj != selfq) {
                        lk[cslot] = k; li[cslot] = jj;
                        float mx = lk[0]; int ms = 0;
#pragma unroll
                        for (int s = 1; s < KSEL; s++) {
                            float v = lk[s];
                            if (v > mx) { mx = v; ms = s; }
                        }
                        cmax = mx; cslot = ms;
                    }
                }
            }
            sh_thr[q] = cmax;
        }
        __syncthreads();
#pragma unroll
        for (int i = 0; i < QR; i++) thr[i] = sh_thr[q0 + i];
    }

    for (int p = t; p < QG * KSEL; p += SCAN_THREADS) {
        int q = p / KSEL, s = p % KSEL;
        int b = qbase + q;
        g_key[inst][b][split][s] = sh_lk[q * LSTR + s];
        g_cid[inst][b][split][s] = sh_li[q * LSTR + s];
    }
}

// ============================================================
// Merge kernel: 4 rows per CTA (256 threads), features + MLP
// ============================================================
__global__ void __launch_bounds__(256)
merge_kernel(const float* __restrict__ emb0, const float* __restrict__ emb1,
             const float* __restrict__ rctx0, const float* __restrict__ rctx1,
             const int* __restrict__ idx0, const int* __restrict__ idx1,
             const float* __restrict__ mean_in, const float* __restrict__ std_in,
             const float* __restrict__ W1, const float* __restrict__ b1v,
             const float* __restrict__ Wm, const float* __restrict__ bm,
             const float* __restrict__ Ws, const float* __restrict__ bs,
             float* __restrict__ out) {
    __shared__ float sh_feat[MROWS][8];
    __shared__ float sh_selk[MROWS][2][KSEL];
    __shared__ int   sh_seli[MROWS][2][KSEL];
    __shared__ float sh_red[MROWS][4];

    int t = threadIdx.x;
    int sb = t >> 6;
    int b = blockIdx.x * MROWS + sb;
    int tl = t & 63;
    int w = tl >> 5;
    int lane = t & 31;

    {
        int inst = w;
        const float* embp = inst ? emb1 : emb0;
        const int*   idxp = inst ? idx1 : idx0;
        int self = idxp[b];

        float av = (lane < EDIM) ? embp[(size_t)self * EDIM + lane] : 0.f;
        float aa = av * av;
#pragma unroll
        for (int off = 16; off > 0; off >>= 1)
            aa += __shfl_down_sync(0xffffffffu, aa, off);
        aa = __shfl_sync(0xffffffffu, aa, 0);

        const float* keys = &g_key[inst][b][0][0];
        const int*   cids = &g_cid[inst][b][0][0];
        float k[NCH]; int id[NCH];
#pragma unroll
        for (int s = 0; s < NCH; s++) {
            int p = lane + 32 * s;
            if (p < NCAND) { k[s] = keys[p]; id[s] = cids[p]; }
            else           { k[s] = CUDART_INF_F; id[s] = 0; }
        }
        for (int iter = 0; iter < KSEL; iter++) {
            float bv = k[0]; int bslot = 0;
#pragma unroll
            for (int s = 1; s < NCH; s++)
                if (k[s] < bv) { bv = k[s]; bslot = s; }
            float v = bv; int owner = lane;
#pragma unroll
            for (int off = 16; off > 0; off >>= 1) {
                float ov = __shfl_down_sync(0xffffffffu, v, off);
                int   ol = __shfl_down_sync(0xffffffffu, owner, off);
                if (ov < v) { v = ov; owner = ol; }
            }
            owner = __shfl_sync(0xffffffffu, owner, 0);
            if (lane == owner) {
                sh_selk[sb][inst][iter] = k[bslot];
                sh_seli[sb][inst][iter] = id[bslot];
                k[bslot] = CUDART_INF_F;
            }
            __syncwarp();
        }
        __syncwarp();

        const float* rctx = inst ? rctx1 : rctx0;
        float wsum = 0.f, swsum = 0.f, ssum = 0.f, s2sum = 0.f;
        if (lane < KSEL) {
            float d2 = sh_selk[sb][inst][lane] + aa;
            d2 = fmaxf(d2, 0.f);
            float sim = sqrtf(d2) + 0.001f;
            float ww = expf(-sim);
            float sel = rctx[(size_t)b * NQ + sh_seli[sb][inst][lane]];
            wsum = ww; swsum = sel * ww; ssum = sel; s2sum = sel * sel;
        }
#pragma unroll
        for (int off = 16; off > 0; off >>= 1) {
            wsum  += __shfl_down_sync(0xffffffffu, wsum,  off);
            swsum += __shfl_down_sync(0xffffffffu, swsum, off);
            ssum  += __shfl_down_sync(0xffffffffu, ssum,  off);
            s2sum += __shfl_down_sync(0xffffffffu, s2sum, off);
        }
        if (lane == 0) {
            float f1 = wsum;
            float f2 = swsum / wsum;
            float var = (s2sum - ssum * ssum / (float)KSEL) / (float)(KSEL - 1);
            float f3 = sqrtf(fmaxf(var, 0.f));
            sh_feat[sb][0 + inst] = f1;
            sh_feat[sb][2 + inst] = f2;
            sh_feat[sb][4 + inst] = f3;
            if (inst == 0) { sh_feat[sb][6] = mean_in[b]; sh_feat[sb][7] = std_in[b]; }
        }
    }
    __syncthreads();

    float h = b1v[tl];
#pragma unroll
    for (int i = 0; i < 8; i++) h = fmaf(sh_feat[sb][i], W1[i * HID + tl], h);
    h = fmaxf(h, 0.f);
    float pm = h * Wm[tl];
    float ps = h * Ws[tl];
#pragma unroll
    for (int off = 16; off > 0; off >>= 1) {
        pm += __shfl_down_sync(0xffffffffu, pm, off);
        ps += __shfl_down_sync(0xffffffffu, ps, off);
    }
    if (lane == 0) { sh_red[sb][w * 2] = pm; sh_red[sb][w * 2 + 1] = ps; }
    __syncthreads();
    if (tl == 0) {
        out[b]      = sh_red[sb][0] + sh_red[sb][2] + bm[0];
        out[BQ + b] = sh_red[sb][1] + sh_red[sb][3] + bs[0];
    }
}

// ============================================================
extern "C" void kernel_launch(void* const* d_in, const int* in_sizes, int n_in,
                              void* d_out, int out_size) {
    const float* emb0    = (const float*)d_in[0];
    const float* emb1    = (const float*)d_in[1];
    const float* rctx0   = (const float*)d_in[2];
    const float* rctx1   = (const float*)d_in[3];
    const int*   idx0    = (const int*)d_in[4];
    const int*   idx1    = (const int*)d_in[5];
    const float* mean_in = (const float*)d_in[6];
    const float* std_in  = (const float*)d_in[7];
    const float* W1      = (const float*)d_in[8];
    const float* b1v     = (const float*)d_in[9];
    const float* Wm      = (const float*)d_in[10];
    const float* bm      = (const float*)d_in[11];
    const float* Ws      = (const float*)d_in[12];
    const float* bs      = (const float*)d_in[13];
    float* out = (float*)d_out;

    scan_kernel<<<64 * NSPLIT, SCAN_THREADS>>>(emb0, emb1, idx0, idx1);
    merge_kernel<<<BQ / MROWS, 256>>>(emb0, emb1, rctx0, rctx1, idx0, idx1,
                                      mean_in, std_in, W1, b1v, Wm, bm, Ws, bs, out);
}

// round 8
// speedup vs baseline: 10.6235x; 1.1304x over previous
#include <cuda_runtime.h>
#include <math_constants.h>

#define NQ    50000
#define NQPAD 50688              // 9 * 5632
#define NT    (NQPAD / 32)       // 1584 tiles of 32 candidates
#define BQ    512
#define EDIM  16
#define KSEL  20
#define QG    16                 // queries per CTA
#define QR    4                  // queries per thread (registers)
#define NSPLIT 9                 // grid = 64*9 = 576
#define CHUNK (NQPAD / NSPLIT)   // 5632 = 22 segments * 256
#define SCAN_THREADS 256
#define CLANES 64
#define SEGQ  256
#define HID   64
#define NCAND (NSPLIT * KSEL)    // 180
#define NCH   6
#define LSTR  21
#define MROWS 4

typedef unsigned long long u64;

// static device scratch
__device__ ulonglong2 g_et[2][NT][4][32];   // tiled embeddings: [tile][dim-quad][lane]
__device__ float      g_een[2][NQPAD];      // squared norms (+INF padding)
__device__ float g_key[2][BQ][NSPLIT][KSEL];
__device__ int   g_cid[2][BQ][NSPLIT][KSEL];

// ---- packed f32x2 helpers ----
__device__ __forceinline__ u64 mul2(u64 a, u64 b) {
    u64 d; asm("mul.rn.f32x2 %0,%1,%2;" : "=l"(d) : "l"(a), "l"(b)); return d;
}
__device__ __forceinline__ u64 fma2(u64 a, u64 b, u64 c) {
    u64 d; asm("fma.rn.f32x2 %0,%1,%2,%3;" : "=l"(d) : "l"(a), "l"(b), "l"(c)); return d;
}
__device__ __forceinline__ u64 add2(u64 a, u64 b) {
    u64 d; asm("add.rn.f32x2 %0,%1,%2;" : "=l"(d) : "l"(a), "l"(b)); return d;
}
__device__ __forceinline__ float hsum2(u64 v) {
    float lo, hi; asm("mov.b64 {%0,%1},%2;" : "=f"(lo), "=f"(hi) : "l"(v));
    return lo + hi;
}
__device__ __forceinline__ u64 pack2(float lo, float hi) {
    u64 d; asm("mov.b64 %0,{%1,%2};" : "=l"(d) : "f"(lo), "f"(hi)); return d;
}

// ============================================================
// Prep kernel: tile-transpose embeddings + precompute norms
// ============================================================
__global__ void prep_kernel(const float* __restrict__ emb0,
                            const float* __restrict__ emb1) {
    int i = blockIdx.x * blockDim.x + threadIdx.x;
    if (i >= 2 * NQPAD) return;
    int inst = i / NQPAD, j = i % NQPAD;
    int tile = j >> 5, lane = j & 31;
    float4 v0 = {0,0,0,0}, v1 = v0, v2 = v0, v3 = v0;
    float ee = CUDART_INF_F;
    if (j < NQ) {
        const float4* e4 = (const float4*)((inst ? emb1 : emb0) + (size_t)j * EDIM);
        v0 = e4[0]; v1 = e4[1]; v2 = e4[2]; v3 = e4[3];
        ee = v0.x*v0.x + v0.y*v0.y + v0.z*v0.z + v0.w*v0.w
           + v1.x*v1.x + v1.y*v1.y + v1.z*v1.z + v1.w*v1.w
           + v2.x*v2.x + v2.y*v2.y + v2.z*v2.z + v2.w*v2.w
           + v3.x*v3.x + v3.y*v3.y + v3.z*v3.z + v3.w*v3.w;
    }
    float4* dst = (float4*)&g_et[inst][tile][0][lane];
    ((float4*)&g_et[inst][tile][0][lane])[0] = v0;
    ((float4*)&g_et[inst][tile][1][lane])[0] = v1;
    ((float4*)&g_et[inst][tile][2][lane])[0] = v2;
    ((float4*)&g_et[inst][tile][3][lane])[0] = v3;
    (void)dst;
    g_een[inst][j] = ee;
}

// ============================================================
// Scan kernel: coalesced tiled loads, queries in registers,
// precomputed norms, deferred queue selection.
// ============================================================
__global__ void __launch_bounds__(SCAN_THREADS, 2)
scan_kernel(const float* __restrict__ emb0, const float* __restrict__ emb1,
            const int* __restrict__ idx0, const int* __restrict__ idx1) {
    __shared__ float sh_lk[QG * LSTR];
    __shared__ int   sh_li[QG * LSTR];
    __shared__ float sh_thr[QG];
    __shared__ int   sh_self[QG];
    __shared__ int   sh_cnt[QG];
    __shared__ float sh_bk[QG][SEGQ + 1];
    __shared__ int   sh_bj[QG][SEGQ + 1];

    int grp   = blockIdx.x / NSPLIT;
    int split = blockIdx.x % NSPLIT;
    int inst  = grp >> 5;
    int qbase = (grp & 31) * QG;
    const float* emb  = inst ? emb1 : emb0;
    const int*   idxp = inst ? idx1 : idx0;
    int base = split * CHUNK;
    int t    = threadIdx.x;
    int cl   = t & (CLANES - 1);
    int lane = t & 31;
    int whalf = (cl >> 5);             // which tile of the round's pair
    int g  = t >> 6;
    int q0 = g * QR;

    if (t < QG) {
        sh_self[t] = idxp[qbase + t];
        sh_cnt[t]  = 0;
        sh_thr[t]  = CUDART_INF_F;
    }
    for (int p = t; p < QG * KSEL; p += SCAN_THREADS) {
        int q = p / KSEL, s = p % KSEL;
        sh_lk[q * LSTR + s] = CUDART_INF_F;
        sh_li[q * LSTR + s] = 0;
    }
    __syncthreads();

    // queries in registers, pre-scaled by -2
    u64 qr[QR][8];
#pragma unroll
    for (int i = 0; i < QR; i++) {
        int qi = sh_self[q0 + i];
        const float* qp = emb + (size_t)qi * EDIM;
#pragma unroll
        for (int d = 0; d < 8; d++)
            qr[i][d] = pack2(-2.0f * qp[2 * d], -2.0f * qp[2 * d + 1]);
    }

    float thr[QR];
#pragma unroll
    for (int i = 0; i < QR; i++) thr[i] = CUDART_INF_F;

    float cmax = CUDART_INF_F;
    int   cslot = 0;

    const ulonglong2* et = &g_et[inst][0][0][0];
    const float*      en = g_een[inst];

    for (int s0 = base; s0 < base + CHUNK; s0 += SEGQ) {
        bool first = (s0 == base);
#pragma unroll
        for (int r = 0; r < SEGQ / CLANES; r++) {
            int j = s0 + r * CLANES + cl;
            int tile = (s0 >> 5) + r * 2 + whalf;
            const ulonglong2* tp = et + ((size_t)tile * 4 * 32 + lane);

            ulonglong2 u0 = tp[0];
            ulonglong2 u1 = tp[32];
            ulonglong2 u2 = tp[64];
            ulonglong2 u3 = tp[96];
            float ee = en[j];
            u64 c0 = u0.x, c1 = u0.y, c2 = u1.x, c3 = u1.y;
            u64 c4 = u2.x, c5 = u2.y, c6 = u3.x, c7 = u3.y;
            u64 eeinit = pack2(ee, 0.0f);

            unsigned pm = 0;
            float kk[QR];
#pragma unroll
            for (int i = 0; i < QR; i++) {
                u64 a = fma2(c0, qr[i][0], eeinit);
                a = fma2(c1, qr[i][1], a);
                a = fma2(c2, qr[i][2], a);
                a = fma2(c3, qr[i][3], a);
                u64 bb = mul2(c4, qr[i][4]);
                bb = fma2(c5, qr[i][5], bb);
                bb = fma2(c6, qr[i][6], bb);
                bb = fma2(c7, qr[i][7], bb);
                float key = hsum2(add2(a, bb));   // = ||e||^2 - 2 a.e
                kk[i] = key;
                pm |= (key < thr[i]) ? (1u << i) : 0u;
            }

            if (first) {
                int slot = r * CLANES + cl;
#pragma unroll
                for (int i = 0; i < QR; i++) {
                    sh_bk[q0 + i][slot] = kk[i];
                    sh_bj[q0 + i][slot] = j;
                }
            } else if (pm) {
                do {
                    int i = __ffs(pm) - 1;
                    pm &= pm - 1;
                    int rr = atomicAdd(&sh_cnt[q0 + i], 1);
                    sh_bk[q0 + i][rr] = kk[i];
                    sh_bj[q0 + i][rr] = j;
                } while (pm);
            }
        }
        __syncthreads();

        // drain: 16 owner threads (2 per warp)
        if ((t & 15) == 0) {
            int q = t >> 4;
            int n = first ? SEGQ : sh_cnt[q];
            sh_cnt[q] = 0;
            int selfq = sh_self[q];
            float* lk = &sh_lk[q * LSTR];
            int*   li = &sh_li[q * LSTR];
            for (int i2 = 0; i2 < n; i2++) {
                float k = sh_bk[q][i2];
                if (k < cmax) {
                    int jj = sh_bj[q][i2];
                    if (jj != selfq) {
                        lk[cslot] = k; li[cslot] = jj;
                        float mx = lk[0]; int ms = 0;
#pragma unroll
                        for (int s = 1; s < KSEL; s++) {
                            float v = lk[s];
                            if (v > mx) { mx = v; ms = s; }
                        }
                        cmax = mx; cslot = ms;
                    }
                }
            }
            sh_thr[q] = cmax;
        }
        __syncthreads();
#pragma unroll
        for (int i = 0; i < QR; i++) thr[i] = sh_thr[q0 + i];
    }

    for (int p = t; p < QG * KSEL; p += SCAN_THREADS) {
        int q = p / KSEL, s = p % KSEL;
        int b = qbase + q;
        g_key[inst][b][split][s] = sh_lk[q * LSTR + s];
        g_cid[inst][b][split][s] = sh_li[q * LSTR + s];
    }
}

// ============================================================
// Merge kernel: 4 rows per CTA (256 threads), features + MLP
// ============================================================
__global__ void __launch_bounds__(256)
merge_kernel(const float* __restrict__ emb0, const float* __restrict__ emb1,
             const float* __restrict__ rctx0, const float* __restrict__ rctx1,
             const int* __restrict__ idx0, const int* __restrict__ idx1,
             const float* __restrict__ mean_in, const float* __restrict__ std_in,
             const float* __restrict__ W1, const float* __restrict__ b1v,
             const float* __restrict__ Wm, const float* __restrict__ bm,
             const float* __restrict__ Ws, const float* __restrict__ bs,
             float* __restrict__ out) {
    __shared__ float sh_feat[MROWS][8];
    __shared__ float sh_selk[MROWS][2][KSEL];
    __shared__ int   sh_seli[MROWS][2][KSEL];
    __shared__ float sh_red[MROWS][4];

    int t = threadIdx.x;
    int sb = t >> 6;
    int b = blockIdx.x * MROWS + sb;
    int tl = t & 63;
    int w = tl >> 5;
    int lane = t & 31;

    {
        int inst = w;
        const int* idxp = inst ? idx1 : idx0;
        int self = idxp[b];
        float aa = g_een[inst][self];

        const float* keys = &g_key[inst][b][0][0];
        const int*   cids = &g_cid[inst][b][0][0];
        float k[NCH]; int id[NCH];
#pragma unroll
        for (int s = 0; s < NCH; s++) {
            int p = lane + 32 * s;
            if (p < NCAND) { k[s] = keys[p]; id[s] = cids[p]; }
            else           { k[s] = CUDART_INF_F; id[s] = 0; }
        }
        for (int iter = 0; iter < KSEL; iter++) {
            float bv = k[0]; int bslot = 0;
#pragma unroll
            for (int s = 1; s < NCH; s++)
                if (k[s] < bv) { bv = k[s]; bslot = s; }
            float v = bv; int owner = lane;
#pragma unroll
            for (int off = 16; off > 0; off >>= 1) {
                float ov = __shfl_down_sync(0xffffffffu, v, off);
                int   ol = __shfl_down_sync(0xffffffffu, owner, off);
                if (ov < v) { v = ov; owner = ol; }
            }
            owner = __shfl_sync(0xffffffffu, owner, 0);
            if (lane == owner) {
                sh_selk[sb][inst][iter] = k[bslot];
                sh_seli[sb][inst][iter] = id[bslot];
                k[bslot] = CUDART_INF_F;
            }
            __syncwarp();
        }
        __syncwarp();

        const float* rctx = inst ? rctx1 : rctx0;
        float wsum = 0.f, swsum = 0.f, ssum = 0.f, s2sum = 0.f;
        if (lane < KSEL) {
            float d2 = sh_selk[sb][inst][lane] + aa;
            d2 = fmaxf(d2, 0.f);
            float sim = sqrtf(d2) + 0.001f;
            float ww = expf(-sim);
            float sel = rctx[(size_t)b * NQ + sh_seli[sb][inst][lane]];
            wsum = ww; swsum = sel * ww; ssum = sel; s2sum = sel * sel;
        }
#pragma unroll
        for (int off = 16; off > 0; off >>= 1) {
            wsum  += __shfl_down_sync(0xffffffffu, wsum,  off);
            swsum += __shfl_down_sync(0xffffffffu, swsum, off);
            ssum  += __shfl_down_sync(0xffffffffu, ssum,  off);
            s2sum += __shfl_down_sync(0xffffffffu, s2sum, off);
        }
        if (lane == 0) {
            float f1 = wsum;
            float f2 = swsum / wsum;
            float var = (s2sum - ssum * ssum / (float)KSEL) / (float)(KSEL - 1);
            float f3 = sqrtf(fmaxf(var, 0.f));
            sh_feat[sb][0 + inst] = f1;
            sh_feat[sb][2 + inst] = f2;
            sh_feat[sb][4 + inst] = f3;
            if (inst == 0) { sh_feat[sb][6] = mean_in[b]; sh_feat[sb][7] = std_in[b]; }
        }
    }
    __syncthreads();

    float h = b1v[tl];
#pragma unroll
    for (int i = 0; i < 8; i++) h = fmaf(sh_feat[sb][i], W1[i * HID + tl], h);
    h = fmaxf(h, 0.f);
    float pm = h * Wm[tl];
    float ps = h * Ws[tl];
#pragma unroll
    for (int off = 16; off > 0; off >>= 1) {
        pm += __shfl_down_sync(0xffffffffu, pm, off);
        ps += __shfl_down_sync(0xffffffffu, ps, off);
    }
    if (lane == 0) { sh_red[sb][w * 2] = pm; sh_red[sb][w * 2 + 1] = ps; }
    __syncthreads();
    if (tl == 0) {
        out[b]      = sh_red[sb][0] + sh_red[sb][2] + bm[0];
        out[BQ + b] = sh_red[sb][1] + sh_red[sb][3] + bs[0];
    }
}

// ============================================================
extern "C" void kernel_launch(void* const* d_in, const int* in_sizes, int n_in,
                              void* d_out, int out_size) {
    const float* emb0    = (const float*)d_in[0];
    const float* emb1    = (const float*)d_in[1];
    const float* rctx0   = (const float*)d_in[2];
    const float* rctx1   = (const float*)d_in[3];
    const int*   idx0    = (const int*)d_in[4];
    const int*   idx1    = (const int*)d_in[5];
    const float* mean_in = (const float*)d_in[6];
    const float* std_in  = (const float*)d_in[7];
    const float* W1      = (const float*)d_in[8];
    const float* b1v     = (const float*)d_in[9];
    const float* Wm      = (const float*)d_in[10];
    const float* bm      = (const float*)d_in[11];
    const float* Ws      = (const float*)d_in[12];
    const float* bs      = (const float*)d_in[13];
    float* out = (float*)d_out;

    prep_kernel<<<(2 * NQPAD + 255) / 256, 256>>>(emb0, emb1);
    scan_kernel<<<64 * NSPLIT, SCAN_THREADS>>>(emb0, emb1, idx0, idx1);
    merge_kernel<<<BQ / MROWS, 256>>>(emb0, emb1, rctx0, rctx1, idx0, idx1,
                                      mean_in, std_in, W1, b1v, Wm, bm, Ws, bs, out);
}